// round 12
// baseline (speedup 1.0000x reference)
#include <cuda_runtime.h>
#include <cstdint>

// ---- static problem config ----
#define HMAP      524288u          // 2^19 entries per level
#define HMASK     (HMAP - 1u)
#define NLEVEL    3
#define NPTS      2097152u         // B
#define TBL_ELEMS (NLEVEL * HMAP)  // 1,572,864
#define NPAIRS    (TBL_ELEMS / 2u) // 786,432
#define PRIME1    2654435761u
#define PRIME2    805459861u

// Pair-packed tables. Tk packs entry pairs {m, m^k} into one aligned float4:
//   Tk[((m & ~k)>>1) + t],  t = min(low, k-low), low = m & k
//   slot lo = member with (m & k) <= k/2; float4 = (lo.c0, lo.c1, hi.c0, hi.c1)
// T1 doubles as the flat float2 table for the scalar fallback.
__device__ __align__(16) float4 g_t1 [NPAIRS];
__device__ __align__(16) float4 g_t3 [NPAIRS];
__device__ __align__(16) float4 g_t7 [NPAIRS];
__device__ __align__(16) float4 g_t15[NPAIRS];

// entry m of the flat multi-level table, read from raw triplane layout
__device__ __forceinline__ float2 ent(const float* __restrict__ tri, unsigned m) {
    unsigned p  = m >> 19;
    unsigned mm = m & HMASK;
    const float* base = tri + (size_t)p * (2u * HMAP);
    return make_float2(base[mm], base[mm + HMAP]);
}

__device__ __forceinline__ float4 pack2(float2 lo, float2 hi) {
    return make_float4(lo.x, lo.y, hi.x, hi.y);
}

// ---------------------------------------------------------------------------
// Pass 1: build the four pair-packed tables from the raw triplane.
// ---------------------------------------------------------------------------
__global__ __launch_bounds__(256) void pack_kernel(const float* __restrict__ tri) {
    unsigned j = blockIdx.x * 256u + threadIdx.x;
    if (j >= NPAIRS) return;

    g_t1[j] = pack2(ent(tri, 2u * j), ent(tri, 2u * j + 1u));
    {   // K=3, group 4
        unsigned b = (j >> 1) << 2, t = j & 1u;
        g_t3[j] = pack2(ent(tri, b + t), ent(tri, b + 3u - t));
    }
    {   // K=7, group 8
        unsigned b = (j >> 2) << 3, t = j & 3u;
        g_t7[j] = pack2(ent(tri, b + t), ent(tri, b + 7u - t));
    }
    {   // K=15, group 16
        unsigned b = (j >> 3) << 4, t = j & 7u;
        g_t15[j] = pack2(ent(tri, b + t), ent(tri, b + 15u - t));
    }
}

// ---------------------------------------------------------------------------
// Pass 2: encode. TWO points per thread; coalesced LDG.64 inputs, one float4
// store. Gathers for BOTH points issued per level before any consumption
// (interleaved, deferred-select: measured best). Selection folded into the
// x-weight: corner contribution = wyz * ( wa*(lo - hi) + hi ).
// ---------------------------------------------------------------------------
__global__ __launch_bounds__(256) void enc_kernel(const float* __restrict__ xin,
                                                  float4* __restrict__ out) {
    const unsigned t = blockIdx.x * 256u + threadIdx.x;   // pair index < NPTS/2

    const float2* __restrict__ x2 = reinterpret_cast<const float2*>(xin);
    const float2 A  = __ldg(&x2[3u * t + 0u]);   // p0.x p0.y
    const float2 Bv = __ldg(&x2[3u * t + 1u]);   // p0.z p1.x
    const float2 Cv = __ldg(&x2[3u * t + 2u]);   // p1.y p1.z

    float cx[2], cy[2], cz[2];
    cx[0] = (A.x  + 1.0f) * 0.5f;  cy[0] = (A.y  + 1.0f) * 0.5f;  cz[0] = (Bv.x + 1.0f) * 0.5f;
    cx[1] = (Bv.y + 1.0f) * 0.5f;  cy[1] = (Cv.x + 1.0f) * 0.5f;  cz[1] = (Cv.y + 1.0f) * 0.5f;

    float accx[2] = {0.0f, 0.0f}, accy[2] = {0.0f, 0.0f};

#pragma unroll
    for (int lv = 0; lv < NLEVEL; lv++) {
        const float scale = (float)((128 << lv) - 1);   // 127, 255, 511

        float4 q [2][4];   // raw pair loads: (lo.c0, lo.c1, hi.c0, hi.c1)
        float  wa[2][4];   // x-weight applied to the lo half
        float  ry[2], rz[2];

        // ---- gather phase: both points' loads issued before any consumption
#pragma unroll
        for (int u = 0; u < 2; u++) {
            const float px = cx[u] * scale + 0.5f;
            const float py = cy[u] * scale + 0.5f;
            const float pz = cz[u] * scale + 0.5f;
            const float gx = floorf(px), gy = floorf(py), gz = floorf(pz);
            const float rx = px - gx;
            ry[u] = py - gy; rz[u] = pz - gz;
            const float wx0 = 1.0f - rx, wx1 = rx;

            const unsigned ix = (unsigned)gx;
            const unsigned iy = (unsigned)gy;
            const unsigned iz = (unsigned)gz;

            const unsigned hy0 = iy * PRIME1;
            const unsigned hy1 = hy0 + PRIME1;
            const unsigned hz0 = iz * PRIME2;
            const unsigned hz1 = hz0 + PRIME2;

            unsigned rr[4];
            rr[0] = hy0 ^ hz0;
            rr[1] = hy1 ^ hz0;
            rr[2] = hy0 ^ hz1;
            rr[3] = hy1 ^ hz1;

            const unsigned lvoff = (unsigned)lv * (HMAP / 2u);
            const unsigned tz = ix ^ (ix + 1u);

            if (tz <= 15u) {
                const float4* __restrict__ tp =
                    (tz == 1u) ? g_t1 : (tz == 3u) ? g_t3 : (tz == 7u) ? g_t7 : g_t15;
                const unsigned half = tz >> 1;
#pragma unroll
                for (int c = 0; c < 4; c++) {
                    const unsigned m   = (ix ^ rr[c]) & HMASK;
                    const unsigned low = m & tz;
                    const bool     hb  = low > half;
                    const unsigned s   = hb ? (tz - low) : low;
                    q[u][c]  = __ldg(&tp[((m & ~tz) >> 1) + s + lvoff]);
                    wa[u][c] = hb ? wx1 : wx0;
                }
            } else {
                // rare (6.25%): ix with >=4 trailing ones -> 8 scalar gathers
                const float2* __restrict__ t2 =
                    reinterpret_cast<const float2*>(g_t1) + (unsigned)lv * HMAP;
                const unsigned ix1 = ix + 1u;
#pragma unroll
                for (int c = 0; c < 4; c++) {
                    const float2 fa = __ldg(&t2[(ix  ^ rr[c]) & HMASK]);
                    const float2 fb = __ldg(&t2[(ix1 ^ rr[c]) & HMASK]);
                    q[u][c]  = make_float4(fa.x, fa.y, fb.x, fb.y);
                    wa[u][c] = wx0;
                }
            }
        }

        // ---- math phase
#pragma unroll
        for (int u = 0; u < 2; u++) {
            const float wy0 = 1.0f - ry[u], wy1 = ry[u];
            const float wz0 = 1.0f - rz[u], wz1 = rz[u];
            float wyz[4];
            wyz[0] = wy0 * wz0;
            wyz[1] = wy1 * wz0;
            wyz[2] = wy0 * wz1;
            wyz[3] = wy1 * wz1;
#pragma unroll
            for (int c = 0; c < 4; c++) {
                const float w = wa[u][c];
                // wa*lo + (1-wa)*hi == wa*(lo-hi) + hi
                accx[u] += wyz[c] * fmaf(w, q[u][c].x - q[u][c].z, q[u][c].z);
                accy[u] += wyz[c] * fmaf(w, q[u][c].y - q[u][c].w, q[u][c].w);
            }
        }
    }

    out[t] = make_float4(accx[0], accy[0], accx[1], accy[1]);
}

extern "C" void kernel_launch(void* const* d_in, const int* in_sizes, int n_in,
                              void* d_out, int out_size) {
    const float* tri = (const float*)d_in[0];
    const float* xin = (const float*)d_in[1];
    if (in_sizes[0] != 3145728) {
        tri = (const float*)d_in[1];
        xin = (const float*)d_in[0];
    }
    float4* out = (float4*)d_out;

    pack_kernel<<<(NPAIRS + 255u) / 256u, 256>>>(tri);
    enc_kernel<<<NPTS / 2u / 256u, 256>>>(xin, out);
}

// round 13
// speedup vs baseline: 1.6213x; 1.6213x over previous
#include <cuda_runtime.h>
#include <cstdint>

// ---- static problem config ----
#define HMAP      524288u          // 2^19 entries per level
#define HMASK     (HMAP - 1u)
#define NLEVEL    3
#define NPTS      2097152u         // B
#define TBL_ELEMS (NLEVEL * HMAP)  // 1,572,864
#define NPAIRS    (TBL_ELEMS / 2u) // 786,432
#define PRIME1    2654435761u
#define PRIME2    805459861u

// Pair-packed tables. Tk packs entry pairs {m, m^k} into one aligned float4:
//   Tk[((m & ~k)>>1) + t],  t = min(low, k-low), low = m & k
//   slot lo = member with (m & k) <= k/2; float4 = (lo.c0, lo.c1, hi.c0, hi.c1)
// T1 doubles as the flat float2 table for the scalar fallback.
__device__ __align__(16) float4 g_t1 [NPAIRS];
__device__ __align__(16) float4 g_t3 [NPAIRS];
__device__ __align__(16) float4 g_t7 [NPAIRS];
__device__ __align__(16) float4 g_t15[NPAIRS];

// entry m of the flat multi-level table, read from raw triplane layout
__device__ __forceinline__ float2 ent(const float* __restrict__ tri, unsigned m) {
    unsigned p  = m >> 19;
    unsigned mm = m & HMASK;
    const float* base = tri + (size_t)p * (2u * HMAP);
    return make_float2(base[mm], base[mm + HMAP]);
}

__device__ __forceinline__ float4 pack2(float2 lo, float2 hi) {
    return make_float4(lo.x, lo.y, hi.x, hi.y);
}

// ---------------------------------------------------------------------------
// Pass 1: build the four pair-packed tables from the raw triplane.
// ---------------------------------------------------------------------------
__global__ __launch_bounds__(256) void pack_kernel(const float* __restrict__ tri) {
    unsigned j = blockIdx.x * 256u + threadIdx.x;
    if (j >= NPAIRS) return;

    g_t1[j] = pack2(ent(tri, 2u * j), ent(tri, 2u * j + 1u));
    {   // K=3, group 4
        unsigned b = (j >> 1) << 2, t = j & 1u;
        g_t3[j] = pack2(ent(tri, b + t), ent(tri, b + 3u - t));
    }
    {   // K=7, group 8
        unsigned b = (j >> 2) << 3, t = j & 3u;
        g_t7[j] = pack2(ent(tri, b + t), ent(tri, b + 7u - t));
    }
    {   // K=15, group 16
        unsigned b = (j >> 3) << 4, t = j & 7u;
        g_t15[j] = pack2(ent(tri, b + t), ent(tri, b + 15u - t));
    }
}

// ---------------------------------------------------------------------------
// Pass 2: encode. TWO points per thread; coalesced LDG.64 inputs, one float4
// store. Gathers for BOTH points issued per level before any consumption
// (interleaved, deferred-select: measured best). Selection folded into the
// x-weight: corner contribution = wyz * ( wa*(lo - hi) + hi ).
// ---------------------------------------------------------------------------
__global__ __launch_bounds__(256) void enc_kernel(const float* __restrict__ xin,
                                                  float4* __restrict__ out) {
    const unsigned t = blockIdx.x * 256u + threadIdx.x;   // pair index < NPTS/2

    const float2* __restrict__ x2 = reinterpret_cast<const float2*>(xin);
    const float2 A  = __ldg(&x2[3u * t + 0u]);   // p0.x p0.y
    const float2 Bv = __ldg(&x2[3u * t + 1u]);   // p0.z p1.x
    const float2 Cv = __ldg(&x2[3u * t + 2u]);   // p1.y p1.z

    float cx[2], cy[2], cz[2];
    cx[0] = (A.x  + 1.0f) * 0.5f;  cy[0] = (A.y  + 1.0f) * 0.5f;  cz[0] = (Bv.x + 1.0f) * 0.5f;
    cx[1] = (Bv.y + 1.0f) * 0.5f;  cy[1] = (Cv.x + 1.0f) * 0.5f;  cz[1] = (Cv.y + 1.0f) * 0.5f;

    float accx[2] = {0.0f, 0.0f}, accy[2] = {0.0f, 0.0f};

#pragma unroll
    for (int lv = 0; lv < NLEVEL; lv++) {
        const float scale = (float)((128 << lv) - 1);   // 127, 255, 511

        float4 q [2][4];   // raw pair loads: (lo.c0, lo.c1, hi.c0, hi.c1)
        float  wa[2][4];   // x-weight applied to the lo half
        float  ry[2], rz[2];

        // ---- gather phase: both points' loads issued before any consumption
#pragma unroll
        for (int u = 0; u < 2; u++) {
            const float px = cx[u] * scale + 0.5f;
            const float py = cy[u] * scale + 0.5f;
            const float pz = cz[u] * scale + 0.5f;
            const float gx = floorf(px), gy = floorf(py), gz = floorf(pz);
            const float rx = px - gx;
            ry[u] = py - gy; rz[u] = pz - gz;
            const float wx0 = 1.0f - rx, wx1 = rx;

            const unsigned ix = (unsigned)gx;
            const unsigned iy = (unsigned)gy;
            const unsigned iz = (unsigned)gz;

            const unsigned hy0 = iy * PRIME1;
            const unsigned hy1 = hy0 + PRIME1;
            const unsigned hz0 = iz * PRIME2;
            const unsigned hz1 = hz0 + PRIME2;

            unsigned rr[4];
            rr[0] = hy0 ^ hz0;
            rr[1] = hy1 ^ hz0;
            rr[2] = hy0 ^ hz1;
            rr[3] = hy1 ^ hz1;

            const unsigned lvoff = (unsigned)lv * (HMAP / 2u);
            const unsigned tz = ix ^ (ix + 1u);

            if (tz <= 15u) {
                const float4* __restrict__ tp =
                    (tz == 1u) ? g_t1 : (tz == 3u) ? g_t3 : (tz == 7u) ? g_t7 : g_t15;
                const unsigned half = tz >> 1;
#pragma unroll
                for (int c = 0; c < 4; c++) {
                    const unsigned m   = (ix ^ rr[c]) & HMASK;
                    const unsigned low = m & tz;
                    const bool     hb  = low > half;
                    const unsigned s   = hb ? (tz - low) : low;
                    q[u][c]  = __ldg(&tp[((m & ~tz) >> 1) + s + lvoff]);
                    wa[u][c] = hb ? wx1 : wx0;
                }
            } else {
                // rare (6.25%): ix with >=4 trailing ones -> 8 scalar gathers
                const float2* __restrict__ t2 =
                    reinterpret_cast<const float2*>(g_t1) + (unsigned)lv * HMAP;
                const unsigned ix1 = ix + 1u;
#pragma unroll
                for (int c = 0; c < 4; c++) {
                    const float2 fa = __ldg(&t2[(ix  ^ rr[c]) & HMASK]);
                    const float2 fb = __ldg(&t2[(ix1 ^ rr[c]) & HMASK]);
                    q[u][c]  = make_float4(fa.x, fa.y, fb.x, fb.y);
                    wa[u][c] = wx0;
                }
            }
        }

        // ---- math phase
#pragma unroll
        for (int u = 0; u < 2; u++) {
            const float wy0 = 1.0f - ry[u], wy1 = ry[u];
            const float wz0 = 1.0f - rz[u], wz1 = rz[u];
            float wyz[4];
            wyz[0] = wy0 * wz0;
            wyz[1] = wy1 * wz0;
            wyz[2] = wy0 * wz1;
            wyz[3] = wy1 * wz1;
#pragma unroll
            for (int c = 0; c < 4; c++) {
                const float w = wa[u][c];
                // wa*lo + (1-wa)*hi == wa*(lo-hi) + hi
                accx[u] += wyz[c] * fmaf(w, q[u][c].x - q[u][c].z, q[u][c].z);
                accy[u] += wyz[c] * fmaf(w, q[u][c].y - q[u][c].w, q[u][c].w);
            }
        }
    }

    out[t] = make_float4(accx[0], accy[0], accx[1], accy[1]);
}

extern "C" void kernel_launch(void* const* d_in, const int* in_sizes, int n_in,
                              void* d_out, int out_size) {
    const float* tri = (const float*)d_in[0];
    const float* xin = (const float*)d_in[1];
    if (in_sizes[0] != 3145728) {
        tri = (const float*)d_in[1];
        xin = (const float*)d_in[0];
    }
    float4* out = (float4*)d_out;

    pack_kernel<<<(NPAIRS + 255u) / 256u, 256>>>(tri);
    enc_kernel<<<NPTS / 2u / 256u, 256>>>(xin, out);
}

// round 15
// speedup vs baseline: 1.6872x; 1.0406x over previous
#include <cuda_runtime.h>
#include <cuda_fp16.h>
#include <cstdint>

// ---- static problem config ----
#define HMAP      524288u          // 2^19 entries per level
#define HMASK     (HMAP - 1u)
#define NLEVEL    3
#define NPTS      2097152u         // B
#define TBL_ELEMS (NLEVEL * HMAP)  // 1,572,864
#define NPAIRS    (TBL_ELEMS / 2u) // 786,432
#define PRIME1    2654435761u
#define PRIME2    805459861u

// Pair-packed HALF-precision tables. Tk packs entry pairs {m, m^k} into one
// aligned uint2: .x = half2(lo.c0, lo.c1), .y = half2(hi.c0, hi.c1),
//   index = ((m & ~k)>>1) + t,  t = min(low, k-low), low = m & k,
//   lo = member with (m & k) <= k/2.
// T1 doubles as the flat half2 table (one uint per entry) for the fallback.
__device__ __align__(8) uint2 g_t1 [NPAIRS];
__device__ __align__(8) uint2 g_t3 [NPAIRS];
__device__ __align__(8) uint2 g_t7 [NPAIRS];
__device__ __align__(8) uint2 g_t15[NPAIRS];

// entry m of the flat multi-level table, read from raw triplane layout,
// quantized to half2 packed in a uint
__device__ __forceinline__ unsigned entq(const float* __restrict__ tri, unsigned m) {
    unsigned p  = m >> 19;
    unsigned mm = m & HMASK;
    const float* base = tri + (size_t)p * (2u * HMAP);
    __half2 h = __floats2half2_rn(base[mm], base[mm + HMAP]);
    return *reinterpret_cast<unsigned*>(&h);
}

__device__ __forceinline__ float2 h2f(unsigned u) {
    __half2 h = *reinterpret_cast<__half2*>(&u);
    return __half22float2(h);
}

// ---------------------------------------------------------------------------
// Pass 1: build the four pair-packed fp16 tables from the raw triplane.
// ---------------------------------------------------------------------------
__global__ __launch_bounds__(256) void pack_kernel(const float* __restrict__ tri) {
    unsigned j = blockIdx.x * 256u + threadIdx.x;
    if (j >= NPAIRS) return;

    g_t1[j] = make_uint2(entq(tri, 2u * j), entq(tri, 2u * j + 1u));
    {   // K=3, group 4
        unsigned b = (j >> 1) << 2, t = j & 1u;
        g_t3[j] = make_uint2(entq(tri, b + t), entq(tri, b + 3u - t));
    }
    {   // K=7, group 8
        unsigned b = (j >> 2) << 3, t = j & 3u;
        g_t7[j] = make_uint2(entq(tri, b + t), entq(tri, b + 7u - t));
    }
    {   // K=15, group 16
        unsigned b = (j >> 3) << 4, t = j & 7u;
        g_t15[j] = make_uint2(entq(tri, b + t), entq(tri, b + 15u - t));
    }
}

// ---------------------------------------------------------------------------
// Pass 2: encode. TWO points per thread; coalesced LDG.64 inputs, one float4
// store. Gathers for BOTH points issued per level before any consumption.
// Math is fp32; table entries are fp16. Selection folded into the x-weight:
// corner contribution = wyz * ( wa*(lo - hi) + hi ).
// ---------------------------------------------------------------------------
__global__ __launch_bounds__(256) void enc_kernel(const float* __restrict__ xin,
                                                  float4* __restrict__ out) {
    const unsigned t = blockIdx.x * 256u + threadIdx.x;   // pair index < NPTS/2

    const float2* __restrict__ x2 = reinterpret_cast<const float2*>(xin);
    const float2 A  = __ldg(&x2[3u * t + 0u]);   // p0.x p0.y
    const float2 Bv = __ldg(&x2[3u * t + 1u]);   // p0.z p1.x
    const float2 Cv = __ldg(&x2[3u * t + 2u]);   // p1.y p1.z

    float cx[2], cy[2], cz[2];
    cx[0] = (A.x  + 1.0f) * 0.5f;  cy[0] = (A.y  + 1.0f) * 0.5f;  cz[0] = (Bv.x + 1.0f) * 0.5f;
    cx[1] = (Bv.y + 1.0f) * 0.5f;  cy[1] = (Cv.x + 1.0f) * 0.5f;  cz[1] = (Cv.y + 1.0f) * 0.5f;

    float accx[2] = {0.0f, 0.0f}, accy[2] = {0.0f, 0.0f};

#pragma unroll
    for (int lv = 0; lv < NLEVEL; lv++) {
        const float scale = (float)((128 << lv) - 1);   // 127, 255, 511

        uint2 q [2][4];    // raw pair loads: (.x = lo half2, .y = hi half2)
        float wa[2][4];    // x-weight applied to the lo half
        float ry[2], rz[2];

        // ---- gather phase: both points' loads issued before any consumption
#pragma unroll
        for (int u = 0; u < 2; u++) {
            const float px = cx[u] * scale + 0.5f;
            const float py = cy[u] * scale + 0.5f;
            const float pz = cz[u] * scale + 0.5f;
            const float gx = floorf(px), gy = floorf(py), gz = floorf(pz);
            const float rx = px - gx;
            ry[u] = py - gy; rz[u] = pz - gz;
            const float wx0 = 1.0f - rx, wx1 = rx;

            const unsigned ix = (unsigned)gx;
            const unsigned iy = (unsigned)gy;
            const unsigned iz = (unsigned)gz;

            const unsigned hy0 = iy * PRIME1;
            const unsigned hy1 = hy0 + PRIME1;
            const unsigned hz0 = iz * PRIME2;
            const unsigned hz1 = hz0 + PRIME2;

            unsigned rr[4];
            rr[0] = hy0 ^ hz0;
            rr[1] = hy1 ^ hz0;
            rr[2] = hy0 ^ hz1;
            rr[3] = hy1 ^ hz1;

            const unsigned lvoff = (unsigned)lv * (HMAP / 2u);
            const unsigned tz = ix ^ (ix + 1u);

            if (tz <= 15u) {
                const uint2* __restrict__ tp =
                    (tz == 1u) ? g_t1 : (tz == 3u) ? g_t3 : (tz == 7u) ? g_t7 : g_t15;
                const unsigned half = tz >> 1;
#pragma unroll
                for (int c = 0; c < 4; c++) {
                    const unsigned m   = (ix ^ rr[c]) & HMASK;
                    const unsigned low = m & tz;
                    const bool     hb  = low > half;
                    const unsigned s   = hb ? (tz - low) : low;
                    q[u][c]  = __ldg(&tp[((m & ~tz) >> 1) + s + lvoff]);
                    wa[u][c] = hb ? wx1 : wx0;
                }
            } else {
                // rare (6.25%): ix with >=4 trailing ones -> 8 scalar gathers
                const unsigned* __restrict__ t2 =
                    reinterpret_cast<const unsigned*>(g_t1) + (unsigned)lv * HMAP;
                const unsigned ix1 = ix + 1u;
#pragma unroll
                for (int c = 0; c < 4; c++) {
                    const unsigned ua = __ldg(&t2[(ix  ^ rr[c]) & HMASK]);
                    const unsigned ub = __ldg(&t2[(ix1 ^ rr[c]) & HMASK]);
                    q[u][c]  = make_uint2(ua, ub);
                    wa[u][c] = wx0;
                }
            }
        }

        // ---- math phase
#pragma unroll
        for (int u = 0; u < 2; u++) {
            const float wy0 = 1.0f - ry[u], wy1 = ry[u];
            const float wz0 = 1.0f - rz[u], wz1 = rz[u];
            float wyz[4];
            wyz[0] = wy0 * wz0;
            wyz[1] = wy1 * wz0;
            wyz[2] = wy0 * wz1;
            wyz[3] = wy1 * wz1;
#pragma unroll
            for (int c = 0; c < 4; c++) {
                const float  w  = wa[u][c];
                const float2 lo = h2f(q[u][c].x);
                const float2 hi = h2f(q[u][c].y);
                // wa*lo + (1-wa)*hi == wa*(lo-hi) + hi
                accx[u] += wyz[c] * fmaf(w, lo.x - hi.x, hi.x);
                accy[u] += wyz[c] * fmaf(w, lo.y - hi.y, hi.y);
            }
        }
    }

    out[t] = make_float4(accx[0], accy[0], accx[1], accy[1]);
}

extern "C" void kernel_launch(void* const* d_in, const int* in_sizes, int n_in,
                              void* d_out, int out_size) {
    const float* tri = (const float*)d_in[0];
    const float* xin = (const float*)d_in[1];
    if (in_sizes[0] != 3145728) {
        tri = (const float*)d_in[1];
        xin = (const float*)d_in[0];
    }
    float4* out = (float4*)d_out;

    pack_kernel<<<(NPAIRS + 255u) / 256u, 256>>>(tri);
    enc_kernel<<<NPTS / 2u / 256u, 256>>>(xin, out);
}